// round 17
// baseline (speedup 1.0000x reference)
#include <cuda_runtime.h>
#include <cuda_bf16.h>

#define BATCH   4096
#define N_OR    21
#define N_ORN   42
#define N_LN    56
#define N_PN    42
#define N_KC    2000
#define N_ODOR  34
#define NSTEPS  20
#define ALPHA   0.9f
#define VTH     1.0f
#define GSOMA   0.3f
#define ISCALE  0.5f

// PN spike masks per (row, step): bit k = PN neuron k
__device__ unsigned long long g_masks[BATCH * NSTEPS];

// ---- packed f32x2 helpers: ONLY fma.rn.f32x2 (the verified pattern) ----
static __device__ __forceinline__ unsigned long long pk2(float lo, float hi) {
    return (unsigned long long)__float_as_uint(lo)
         | ((unsigned long long)__float_as_uint(hi) << 32);
}
static __device__ __forceinline__ float lo2(unsigned long long v) {
    return __uint_as_float((unsigned)v);
}
static __device__ __forceinline__ float hi2(unsigned long long v) {
    return __uint_as_float((unsigned)(v >> 32));
}
static __device__ __forceinline__ unsigned long long fma2(
    unsigned long long a, unsigned long long b, unsigned long long c) {
    unsigned long long r;
    asm("fma.rn.f32x2 %0,%1,%2,%3;" : "=l"(r) : "l"(a), "l"(b), "l"(c));
    return r;
}
#define ONE2   0x3F8000003F800000ull   /* { 1.0f, 1.0f} */
#define NEG12  0xBF800000BF800000ull   /* {-1.0f,-1.0f} */
#define ZERO2  0x0000000000000000ull

// spread 21-bit value to even bit positions of a 64-bit word
__device__ __forceinline__ unsigned long long spread21(unsigned x) {
    unsigned long long v = x & 0x1FFFFFu;
    v = (v | (v << 16)) & 0x0000FFFF0000FFFFull;
    v = (v | (v << 8))  & 0x00FF00FF00FF00FFull;
    v = (v | (v << 4))  & 0x0F0F0F0F0F0F0F0Full;
    v = (v | (v << 2))  & 0x3333333333333333ull;
    v = (v | (v << 1))  & 0x5555555555555555ull;
    return v;
}

// ---------------------------------------------------------------------------
// Kernel 1: ORN/LN/PN cascade. One warp per row. ORN 2i,2i+1 share drive ->
// one state per OR, weight rows pair-summed, packed u64 tiles + fma2 loops.
// Complement-sum on BOTH hot loops: ORN loop (popc>10 -> iterate complement;
// steady state = all fire = 0 iterations) and LN->PN loop (popc>28).
// ---------------------------------------------------------------------------
__global__ __launch_bounds__(256) void k1_masks(
    const float* __restrict__ or_input, const float* __restrict__ or_gains,
    const float* __restrict__ orn_to_pn, const float* __restrict__ orn_to_ln,
    const float* __restrict__ ln_to_pn)
{
    __shared__ unsigned long long sOLp[N_OR][32];  // pair-summed orn_to_ln (28 used)
    __shared__ unsigned long long sOPp[N_OR][32];  // pair-summed orn_to_pn (21 used)
    __shared__ unsigned long long sLP[N_LN][32];   // ln_to_pn rows (21 used)
    __shared__ unsigned long long sOLtot[32], sOPtot[32], sLPtot[32];
    __shared__ float sSg[N_OR];

    int tid = threadIdx.x;
    for (int i = tid; i < N_OR * 32; i += 256) {
        int p = i >> 5, c = i & 31;
        float ax = 0.f, ay = 0.f, bx = 0.f, by = 0.f;
        if (c < 28) {
            float2 r0 = ((const float2*)(orn_to_ln + (2 * p)     * N_LN))[c];
            float2 r1 = ((const float2*)(orn_to_ln + (2 * p + 1) * N_LN))[c];
            ax = r0.x + r1.x; ay = r0.y + r1.y;
        }
        if (c < 21) {
            float2 r0 = ((const float2*)(orn_to_pn + (2 * p)     * N_PN))[c];
            float2 r1 = ((const float2*)(orn_to_pn + (2 * p + 1) * N_PN))[c];
            bx = r0.x + r1.x; by = r0.y + r1.y;
        }
        sOLp[p][c] = pk2(ax, ay);
        sOPp[p][c] = pk2(bx, by);
    }
    for (int i = tid; i < N_LN * 32; i += 256) {
        int r = i >> 5, c = i & 31;
        float wx = 0.f, wy = 0.f;
        if (c < 21) {
            float2 w = ((const float2*)(ln_to_pn + r * N_PN))[c];
            wx = w.x; wy = w.y;
        }
        sLP[r][c] = pk2(wx, wy);
    }
    if (tid < N_OR) sSg[tid] = log1pf(expf(or_gains[tid]));  // softplus
    __syncthreads();
    if (tid < 32) {
        float ax = 0.f, ay = 0.f, bx = 0.f, by = 0.f;
        for (int p = 0; p < N_OR; p++) {
            ax += lo2(sOLp[p][tid]); ay += hi2(sOLp[p][tid]);
            bx += lo2(sOPp[p][tid]); by += hi2(sOPp[p][tid]);
        }
        sOLtot[tid] = pk2(ax, ay);
        sOPtot[tid] = pk2(bx, by);
        float cx = 0.f, cy = 0.f;
        for (int r = 0; r < N_LN; r++) {
            cx += lo2(sLP[r][tid]); cy += hi2(sLP[r][tid]);
        }
        sLPtot[tid] = pk2(cx, cy);
    }
    __syncthreads();

    int warp = tid >> 5, lane = tid & 31;
    int row = (blockIdx.x << 3) + warp;

    float d = (lane < N_OR)
            ? or_input[row * N_OR + lane] * sSg[lane] * ISCALE : 0.f;

    float vO = 0.f;
    unsigned long long vL2 = ZERO2, vP2 = ZERO2;
    unsigned long long* mout = g_masks + (size_t)row * NSTEPS;

    for (int t = 0; t < NSTEPS; t++) {
        // ORN LIF (one state per OR pair)
        vO = ALPHA * vO + d;
        bool sO = (vO - VTH) > 0.f;
        unsigned bO = __ballot_sync(0xFFFFFFFFu, sO) & 0x1FFFFFu;
        if (sO) vO = 0.f;

        // merged LN drive + PN excitation: direct or complement (uniform)
        unsigned long long aL2 = ZERO2, eE2 = ZERO2;
        bool compO = __popc(bO) > 10;
        unsigned m = compO ? (~bO & 0x1FFFFFu) : bO;
        while (m) {
            int p = __ffs(m) - 1; m &= m - 1;
            aL2 = fma2(ONE2, sOLp[p][lane], aL2);
            eE2 = fma2(ONE2, sOPp[p][lane], eE2);
        }
        if (compO) {
            aL2 = fma2(NEG12, aL2, sOLtot[lane]);   // tot - acc
            eE2 = fma2(NEG12, eE2, sOPtot[lane]);
        }

        // LN LIF: vL = ALPHA*vL + aL
        vL2 = fma2(pk2(ALPHA, ALPHA), vL2, aL2);
        {
            float x = lo2(vL2), y = hi2(vL2);
            bool sx = (x - VTH) > 0.f, sy = (y - VTH) > 0.f;
            unsigned bLx = __ballot_sync(0xFFFFFFFFu, sx) & 0x0FFFFFFFu;
            unsigned bLy = __ballot_sync(0xFFFFFFFFu, sy) & 0x0FFFFFFFu;
            vL2 = pk2(sx ? 0.f : x, sy ? 0.f : y);

            // LN->PN inhibition: direct or complement (uniform branch)
            unsigned long long iI2;
            int nb = __popc(bLx) + __popc(bLy);
            if (nb > 28) {
                iI2 = sLPtot[lane];
                m = ~bLx & 0x0FFFFFFFu;
                while (m) {
                    int p = __ffs(m) - 1; m &= m - 1;
                    iI2 = fma2(NEG12, sLP[2 * p][lane], iI2);
                }
                m = ~bLy & 0x0FFFFFFFu;
                while (m) {
                    int p = __ffs(m) - 1; m &= m - 1;
                    iI2 = fma2(NEG12, sLP[2 * p + 1][lane], iI2);
                }
            } else {
                iI2 = ZERO2;
                m = bLx;
                while (m) {
                    int p = __ffs(m) - 1; m &= m - 1;
                    iI2 = fma2(ONE2, sLP[2 * p][lane], iI2);
                }
                m = bLy;
                while (m) {
                    int p = __ffs(m) - 1; m &= m - 1;
                    iI2 = fma2(ONE2, sLP[2 * p + 1][lane], iI2);
                }
            }

            // PN LIF: vP = (ALPHA*vP + eE) - iI
            vP2 = fma2(pk2(ALPHA, ALPHA), vP2, eE2);
            vP2 = fma2(NEG12, iI2, vP2);
        }
        {
            float x = lo2(vP2), y = hi2(vP2);
            bool sx = (x - VTH) > 0.f, sy = (y - VTH) > 0.f;
            unsigned bPx = __ballot_sync(0xFFFFFFFFu, sx) & 0x1FFFFFu;
            unsigned bPy = __ballot_sync(0xFFFFFFFFu, sy) & 0x1FFFFFu;
            vP2 = pk2(sx ? 0.f : x, sy ? 0.f : y);

            if (lane == 0)
                mout[t] = spread21(bPx) | (spread21(bPy) << 1);
        }
    }
}

// ---------------------------------------------------------------------------
// Kernel 2: KC dynamics + APL + decode. One CTA/row, 8 KC cols/thread.
// Fully packed step body: spike/reset/count/part via FSETP+FSEL producing
// s in {-1,0} then 3 fma2 per u64 (va=s*va+va, cnt+=1 via (-1)*s, part+=aplw
// via s*(-aplw)). APL broadcast read as packed u64 adds. Prefetch-before-
// barrier, one barrier/step, warp-sliced decode (34 cols).
// ---------------------------------------------------------------------------
__global__ __launch_bounds__(256, 4) void k2_kc(
    const float* __restrict__ pn_to_kc, const float* __restrict__ kc_to_apl,
    const float* __restrict__ apl_to_kc, const float* __restrict__ dec_w,
    const float* __restrict__ dec_b, float* __restrict__ out)
{
    __shared__ int   sCnt[NSTEPS + 1];
    __shared__ int   sOff[NSTEPS + 1][N_PN];
    __shared__ __align__(16) float sW[2][8];
    __shared__ int   sT0;
    __shared__ int   sWTot[8];
    __shared__ int   sIdx[2048];
    __shared__ float sRate[2048];
    __shared__ float sLg[8][N_ODOR];

    int tid = threadIdx.x;
    int lane = tid & 31, wid = tid >> 5;
    int row = blockIdx.x;

    if (tid < 8) { sW[0][tid] = 0.f; sW[1][tid] = 0.f; }
    if (tid < 32) {
        int n = 0;
        if (tid < NSTEPS) {
            unsigned long long m = g_masks[(size_t)row * NSTEPS + tid];
            while (m) {
                int k = __ffsll((long long)m) - 1; m &= m - 1;
                sOff[tid][n++] = k * (N_KC * 4);   // byte offset of weight row
            }
            sCnt[tid] = n;
        }
        if (tid == NSTEPS) sCnt[NSTEPS] = 0;
        unsigned nz = __ballot_sync(0xFFFFFFFFu, n > 0);
        if (tid == 0) sT0 = nz ? (__ffs(nz) - 1) : NSTEPS;
    }
    __syncthreads();

    int t0 = sT0;
    if (t0 >= NSTEPS) {   // no PN spikes ever -> logits = dec_b
        if (tid < N_ODOR) out[(size_t)row * N_ODOR + tid] = dec_b[tid];
        return;
    }

    int c0 = tid * 8;
    bool valid = (c0 < N_KC);
    const char* wbase = (const char*)(pn_to_kc + (valid ? c0 : 0));
    const float* aplkp = apl_to_kc + (valid ? c0 : 0);
    const float* aplwp = kc_to_apl + (valid ? c0 : 0);

    unsigned long long aplk0 = 0, aplk1 = 0, aplk2 = 0, aplk3 = 0;
    unsigned long long nw0 = 0, nw1 = 0, nw2 = 0, nw3 = 0;  // -aplw packed
    if (valid) {
        aplk0 = pk2(aplkp[0], aplkp[1]);
        aplk1 = pk2(aplkp[2], aplkp[3]);
        aplk2 = pk2(aplkp[4], aplkp[5]);
        aplk3 = pk2(aplkp[6], aplkp[7]);
        nw0 = pk2(-aplwp[0], -aplwp[1]);
        nw1 = pk2(-aplwp[2], -aplwp[3]);
        nw2 = pk2(-aplwp[4], -aplwp[5]);
        nw3 = pk2(-aplwp[6], -aplwp[7]);
    }

    unsigned long long vd0 = 0, vd1 = 0, vd2 = 0, vd3 = 0;
    unsigned long long va0 = 0, va1 = 0, va2 = 0, va3 = 0;
    unsigned long long cnt0 = 0, cnt1 = 0, cnt2p = 0, cnt3 = 0; // packed float counters

    const unsigned long long ALPHA2 = pk2(ALPHA, ALPHA);
    const unsigned long long AG2    = pk2(ALPHA - GSOMA, ALPHA - GSOMA);
    const unsigned long long G2     = pk2(GSOMA, GSOMA);

    // prefetch step t0 rows into vd (state is exactly zero before t0)
    if (valid) {
        int n = sCnt[t0];
        for (int i = 0; i < n; i++) {
            int off = sOff[t0][i];
            float4 a = __ldg((const float4*)(wbase + off));
            float4 b = __ldg((const float4*)(wbase + off + 16));
            vd0 = fma2(ONE2, pk2(a.x, a.y), vd0);
            vd1 = fma2(ONE2, pk2(a.z, a.w), vd1);
            vd2 = fma2(ONE2, pk2(b.x, b.y), vd2);
            vd3 = fma2(ONE2, pk2(b.z, b.w), vd3);
        }
    }

    for (int t = t0; t < NSTEPS; t++) {
        // APL from previous step: packed pairwise sum (deterministic)
        const unsigned long long* wp2 =
            (const unsigned long long*)sW[(t + 1) & 1];
        unsigned long long u = fma2(ONE2, wp2[0], wp2[1]);
        unsigned long long v = fma2(ONE2, wp2[2], wp2[3]);
        unsigned long long s = fma2(ONE2, u, v);
        float apl = lo2(s) + hi2(s);

        // vd -= apl * aplk  (apl==0 is an exact no-op)
        unsigned long long napl2 = pk2(-apl, -apl);
        vd0 = fma2(napl2, aplk0, vd0);
        vd1 = fma2(napl2, aplk1, vd1);
        vd2 = fma2(napl2, aplk2, vd2);
        vd3 = fma2(napl2, aplk3, vd3);

        // axon compartment: va = (ALPHA-GSOMA)*va + GSOMA*vd
        va0 = fma2(AG2, va0, fma2(G2, vd0, ZERO2));
        va1 = fma2(AG2, va1, fma2(G2, vd1, ZERO2));
        va2 = fma2(AG2, va2, fma2(G2, vd2, ZERO2));
        va3 = fma2(AG2, va3, fma2(G2, vd3, ZERO2));

        // packed spike/reset/count/part: s in {-1,0} per value
        unsigned long long part2 = ZERO2;
        {
            float x, y, sxn, syn;
            unsigned long long sn;
            x = lo2(va0); y = hi2(va0);
            sxn = ((x - VTH) > 0.f) ? -1.f : 0.f;
            syn = ((y - VTH) > 0.f) ? -1.f : 0.f;
            sn = pk2(sxn, syn);
            va0  = fma2(sn, va0, va0);        // va *= (1-s): exact 0 on spike
            cnt0 = fma2(NEG12, sn, cnt0);     // cnt += 1 on spike (exact)
            part2 = fma2(sn, nw0, part2);     // part += aplw on spike

            x = lo2(va1); y = hi2(va1);
            sxn = ((x - VTH) > 0.f) ? -1.f : 0.f;
            syn = ((y - VTH) > 0.f) ? -1.f : 0.f;
            sn = pk2(sxn, syn);
            va1  = fma2(sn, va1, va1);
            cnt1 = fma2(NEG12, sn, cnt1);
            part2 = fma2(sn, nw1, part2);

            x = lo2(va2); y = hi2(va2);
            sxn = ((x - VTH) > 0.f) ? -1.f : 0.f;
            syn = ((y - VTH) > 0.f) ? -1.f : 0.f;
            sn = pk2(sxn, syn);
            va2   = fma2(sn, va2, va2);
            cnt2p = fma2(NEG12, sn, cnt2p);
            part2 = fma2(sn, nw2, part2);

            x = lo2(va3); y = hi2(va3);
            sxn = ((x - VTH) > 0.f) ? -1.f : 0.f;
            syn = ((y - VTH) > 0.f) ? -1.f : 0.f;
            sn = pk2(sxn, syn);
            va3  = fma2(sn, va3, va3);
            cnt3 = fma2(NEG12, sn, cnt3);
            part2 = fma2(sn, nw3, part2);
        }
        float part = lo2(part2) + hi2(part2);
        #pragma unroll
        for (int o = 16; o; o >>= 1)
            part += __shfl_xor_sync(0xFFFFFFFFu, part, o);
        if (lane == 0) sW[t & 1][wid] = part;

        // pre-accumulate next step BEFORE barrier: vd = ALPHA*vd + rows(t+1)
        vd0 = fma2(ALPHA2, vd0, ZERO2);
        vd1 = fma2(ALPHA2, vd1, ZERO2);
        vd2 = fma2(ALPHA2, vd2, ZERO2);
        vd3 = fma2(ALPHA2, vd3, ZERO2);
        int n = sCnt[t + 1];          // sCnt[NSTEPS] == 0
        if (valid) {
            for (int i = 0; i < n; i++) {
                int off = sOff[t + 1][i];
                float4 a = __ldg((const float4*)(wbase + off));
                float4 b = __ldg((const float4*)(wbase + off + 16));
                vd0 = fma2(ONE2, pk2(a.x, a.y), vd0);
                vd1 = fma2(ONE2, pk2(a.z, a.w), vd1);
                vd2 = fma2(ONE2, pk2(b.x, b.y), vd2);
                vd3 = fma2(ONE2, pk2(b.z, b.w), vd3);
            }
        }
        __syncthreads();
    }

    // ---- unpack packed counters ----
    float cntf[8];
    cntf[0] = lo2(cnt0);  cntf[1] = hi2(cnt0);
    cntf[2] = lo2(cnt1);  cntf[3] = hi2(cnt1);
    cntf[4] = lo2(cnt2p); cntf[5] = hi2(cnt2p);
    cntf[6] = lo2(cnt3);  cntf[7] = hi2(cnt3);

    // ---- compact active KCs (deterministic, ascending kc index) ----
    int act = 0;
    #pragma unroll
    for (int j = 0; j < 8; j++) if (cntf[j] > 0.f) act++;

    int x = act;
    #pragma unroll
    for (int dlt = 1; dlt < 32; dlt <<= 1) {
        int y = __shfl_up_sync(0xFFFFFFFFu, x, dlt);
        if (lane >= dlt) x += y;
    }
    if (lane == 31) sWTot[wid] = x;
    __syncthreads();
    int base = 0;
    #pragma unroll
    for (int w = 0; w < 8; w++) if (w < wid) base += sWTot[w];
    int pos = base + x - act;
    #pragma unroll
    for (int j = 0; j < 8; j++) {
        if (cntf[j] > 0.f) {
            sIdx[pos]  = c0 + j;
            sRate[pos] = cntf[j] * (1.f / NSTEPS);
            pos++;
        }
    }
    __syncthreads();

    // ---- decode split over 8 warps (fixed slices -> deterministic) ----
    // lane covers odor `lane`; lanes 0-1 ALSO cover odors 32-33 (N_ODOR=34).
    int K = 0;
    #pragma unroll
    for (int w = 0; w < 8; w++) K += sWTot[w];
    int per = (K + 7) >> 3;
    int beg = wid * per;
    int end = min(K, beg + per);
    float acc0 = 0.f, acc1 = 0.f;
    for (int i = beg; i < end; i++) {
        float r = sRate[i];
        const float* dw = dec_w + sIdx[i] * N_ODOR;
        acc0 = fmaf(r, __ldg(dw + lane), acc0);
        if (lane < N_ODOR - 32)
            acc1 = fmaf(r, __ldg(dw + 32 + lane), acc1);
    }
    sLg[wid][lane] = acc0;
    if (lane < N_ODOR - 32) sLg[wid][32 + lane] = acc1;
    __syncthreads();
    if (tid < N_ODOR) {
        float su = 0.f;
        #pragma unroll
        for (int w = 0; w < 8; w++) su += sLg[w][tid];
        out[(size_t)row * N_ODOR + tid] = su + dec_b[tid];
    }
}

extern "C" void kernel_launch(void* const* d_in, const int* in_sizes, int n_in,
                              void* d_out, int out_size) {
    const float* or_input  = (const float*)d_in[0];   // [4096, 21]
    const float* or_gains  = (const float*)d_in[1];   // [21]
    // d_in[2] = mapping [21,42] — fixed OR i -> ORN 2i,2i+1 (folded into k1)
    const float* orn_to_pn = (const float*)d_in[3];   // [42, 42]
    const float* orn_to_ln = (const float*)d_in[4];   // [42, 56]
    const float* ln_to_pn  = (const float*)d_in[5];   // [56, 42]
    const float* pn_to_kc  = (const float*)d_in[6];   // [42, 2000]
    const float* kc_to_apl = (const float*)d_in[7];   // [2000, 1]
    const float* apl_to_kc = (const float*)d_in[8];   // [1, 2000]
    const float* dec_w     = (const float*)d_in[9];   // [2000, 34]
    const float* dec_b     = (const float*)d_in[10];  // [34]
    float* out = (float*)d_out;                       // [4096, 34]

    k1_masks<<<BATCH / 8, 256>>>(or_input, or_gains,
                                 orn_to_pn, orn_to_ln, ln_to_pn);
    k2_kc<<<BATCH, 256>>>(pn_to_kc, kc_to_apl, apl_to_kc, dec_w, dec_b, out);
}